// round 13
// baseline (speedup 1.0000x reference)
#include <cuda_runtime.h>
#include <math.h>

#define FDIM 256
#define BMAX 1024
#define MMAX 500000
#define NMAX 200000
#define CPW  16      // candidates per dot-warp (4 iterations x 4)
#define PREBLK 1024  // blocks doing per-node precompute inside k_fused

// Scratch (allocation-free: __device__ globals)
__device__ float    g_groot[BMAX * FDIM];   // per-root x_r * w_ego_root * w_ego_u
__device__ float2   g_rootsc[BMAX];         // {1/max(nr,eps), budgets/200}
__device__ float    g_sv[BMAX];             // x_r . w_layer_v
__device__ unsigned g_pnorm[BMAX];          // encoded float max
__device__ float    g_agg[MMAX];            // segment_sum(sv[edge_src] -> edge_dst)
__device__ float    g_dot[MMAX];            // raw dot(x_u, g_b)
__device__ float    g_pu[MMAX];             // p_u before normalization
__device__ float4   g_node[NMAX];           // {1/max(nu,eps), su, 0.5*n_imp, 0}

__device__ __forceinline__ unsigned f2key(float f) {
    unsigned u = __float_as_uint(f);
    return (u & 0x80000000u) ? ~u : (u | 0x80000000u);
}
__device__ __forceinline__ float key2f(unsigned k) {
    unsigned u = (k & 0x80000000u) ? (k ^ 0x80000000u) : ~k;
    return __uint_as_float(u);
}
__device__ __forceinline__ float dot4(float4 a, float4 b) {
    return a.x * b.x + a.y * b.y + a.z * b.z + a.w * b.w;
}
__device__ __forceinline__ float sq4(float4 a, float4 w) {
    float t0 = a.x * w.x, t1 = a.y * w.y, t2 = a.z * w.z, t3 = a.w * w.w;
    return t0 * t0 + t1 * t1 + t2 * t2 + t3 * t3;
}

// K1: per-root precompute (one block per root) + zero g_agg (strided).
__global__ void k_root(const float* __restrict__ x,
                       const float* __restrict__ w_ego_root,
                       const float* __restrict__ w_ego_u,
                       const float* __restrict__ w_layer_v,
                       const float* __restrict__ budgets,
                       const int*   __restrict__ batch_nodes,
                       int B, int M)
{
    int b = blockIdx.x;
    int f = threadIdx.x;

    for (int j = b * FDIM + f; j < M; j += gridDim.x * FDIM) g_agg[j] = 0.0f;

    float xr = x[(size_t)batch_nodes[b] * FDIM + f];
    float h  = xr * w_ego_root[f];
    g_groot[b * FDIM + f] = h * w_ego_u[f];
    float s1 = h * h;
    float s2 = xr * w_layer_v[f];

    __shared__ float sh1[8], sh2[8];
    #pragma unroll
    for (int o = 16; o; o >>= 1) {
        s1 += __shfl_xor_sync(0xffffffffu, s1, o);
        s2 += __shfl_xor_sync(0xffffffffu, s2, o);
    }
    int w = f >> 5, l = f & 31;
    if (l == 0) { sh1[w] = s1; sh2[w] = s2; }
    __syncthreads();
    if (f == 0) {
        float t1 = 0.f, t2 = 0.f;
        #pragma unroll
        for (int i = 0; i < 8; i++) { t1 += sh1[i]; t2 += sh2[i]; }
        g_rootsc[b] = make_float2(1.0f / fmaxf(sqrtf(t1), 1e-6f),
                                  budgets[b] * (1.0f / 200.0f));
        g_sv[b] = t2;
        g_pnorm[b] = f2key(-INFINITY);
    }
}

// K2: one kernel, three independent groups, STRIPE-INTERLEAVED so every
// scheduling wave carries a mix of dot (L2 gather), pre (DRAM stream),
// and edge (L2 atomics) blocks:
//   linear in [0, nDot)                   candidate dot gather
//   linear in [nDot, nDot+PREBLK)         per-node {invnu, su, n_imp}
//   linear in [nDot+PREBLK, G)            edge scatter-add
__global__ void __launch_bounds__(256)
k_fused(const float* __restrict__ x,
        const float* __restrict__ w_ego_u,
        const float* __restrict__ w_layer_u,
        const float* __restrict__ n_imp,
        const int* __restrict__ edge_src,
        const int* __restrict__ edge_dst,
        const int* __restrict__ u_ids,
        const int* __restrict__ batch_ptr,
        int N, int E, int M, int nDotBlk, int G, int stripeSize)
{
    // 8-stripe interleave: consecutive launch-order blocks span the range
    int linear = (int)(blockIdx.x & 7) * stripeSize + (int)(blockIdx.x >> 3);
    if (linear >= G) return;

    const float4* x4 = (const float4*)x;

    if (linear < nDotBlk) {
        // ---- candidate dots: 8-lanes-per-candidate, 4 cands/warp-iter ----
        int lane  = threadIdx.x & 31;
        int gwarp = linear * 8 + (threadIdx.x >> 5);
        int c = lane >> 3;          // candidate slot 0..3
        int s = lane & 7;           // sublane 0..7
        const float4* g4 = (const float4*)g_groot;

        int Mmain = M & ~3;

        // tail: grid-warp 0 handles [Mmain, M) with a 32-lane path
        if (gwarp == 0 && Mmain < M) {
            for (int m = Mmain; m < M; m++) {
                int u = __ldg(u_ids + m);
                int b = __ldg(batch_ptr + m);
                float4 xa = __ldg(x4 + (size_t)u * 64 + lane);
                float4 xb = __ldg(x4 + (size_t)u * 64 + lane + 32);
                float4 ta = __ldg(g4 + (size_t)b * 64 + lane);
                float4 tb = __ldg(g4 + (size_t)b * 64 + lane + 32);
                float d = dot4(xa, ta) + dot4(xb, tb);
                #pragma unroll
                for (int o = 16; o; o >>= 1)
                    d += __shfl_xor_sync(0xffffffffu, d, o);
                if (lane == 0) g_dot[m] = d;
            }
        }

        int base = gwarp * CPW;
        if (base >= Mmain) return;
        int lim = base + CPW; if (lim > Mmain) lim = Mmain;

        for (int m0 = base; m0 < lim; m0 += 4) {
            int4 uu = *(const int4*)(u_ids + m0);
            int4 bb = *(const int4*)(batch_ptr + m0);
            int u = (c == 0) ? uu.x : (c == 1) ? uu.y : (c == 2) ? uu.z : uu.w;
            int b = (c == 0) ? bb.x : (c == 1) ? bb.y : (c == 2) ? bb.z : bb.w;

            const float4* xr = x4 + (size_t)u * 64 + s;
            float4 xv0 = __ldg(xr);
            float4 xv1 = __ldg(xr + 8);
            float4 xv2 = __ldg(xr + 16);
            float4 xv3 = __ldg(xr + 24);
            float4 xv4 = __ldg(xr + 32);
            float4 xv5 = __ldg(xr + 40);
            float4 xv6 = __ldg(xr + 48);
            float4 xv7 = __ldg(xr + 56);

            const float4* gr = g4 + (size_t)b * 64 + s;
            float dot = dot4(xv0, __ldg(gr))
                      + dot4(xv1, __ldg(gr + 8))
                      + dot4(xv2, __ldg(gr + 16))
                      + dot4(xv3, __ldg(gr + 24))
                      + dot4(xv4, __ldg(gr + 32))
                      + dot4(xv5, __ldg(gr + 40))
                      + dot4(xv6, __ldg(gr + 48))
                      + dot4(xv7, __ldg(gr + 56));

            #pragma unroll
            for (int o = 4; o; o >>= 1)
                dot += __shfl_xor_sync(0xffffffffu, dot, o);

            if (s == 0) g_dot[m0 + c] = dot;   // 4 lanes, 16B coalesced
        }
    } else if (linear < nDotBlk + PREBLK) {
        // ---- per-node precompute: {invnu, su, 0.5*n_imp} ----
        int lane = threadIdx.x & 31;
        int gw = (linear - nDotBlk) * 8 + (threadIdx.x >> 5);
        int nw = PREBLK * 8;

        float4 wea = __ldg(((const float4*)w_ego_u)   + lane);
        float4 web = __ldg(((const float4*)w_ego_u)   + lane + 32);
        float4 wla = __ldg(((const float4*)w_layer_u) + lane);
        float4 wlb = __ldg(((const float4*)w_layer_u) + lane + 32);

        for (int n = gw * 2; n < N; n += nw * 2) {
            bool two = (n + 1 < N);
            float4 a0 = __ldg(x4 + (size_t)n * 64 + lane);
            float4 b0 = __ldg(x4 + (size_t)n * 64 + lane + 32);
            int n1 = two ? n + 1 : n;
            float4 a1 = __ldg(x4 + (size_t)n1 * 64 + lane);
            float4 b1 = __ldg(x4 + (size_t)n1 * 64 + lane + 32);

            float nu0 = sq4(a0, wea) + sq4(b0, web);
            float su0 = dot4(a0, wla) + dot4(b0, wlb);
            float nu1 = sq4(a1, wea) + sq4(b1, web);
            float su1 = dot4(a1, wla) + dot4(b1, wlb);

            nu0 += __shfl_xor_sync(0xffffffffu, nu0, 16);
            su0 += __shfl_xor_sync(0xffffffffu, su0, 16);
            nu1 += __shfl_xor_sync(0xffffffffu, nu1, 16);
            su1 += __shfl_xor_sync(0xffffffffu, su1, 16);
            bool hi16 = (lane & 16) != 0;
            float v0 = hi16 ? su0 : nu0;      // lanes<16: nu, >=16: su
            float v1 = hi16 ? su1 : nu1;
            #pragma unroll
            for (int o = 8; o; o >>= 1) {
                v0 += __shfl_xor_sync(0xffffffffu, v0, o);
                v1 += __shfl_xor_sync(0xffffffffu, v1, o);
            }
            float su0f = __shfl_sync(0xffffffffu, v0, 16);
            float su1f = __shfl_sync(0xffffffffu, v1, 16);
            if (lane == 0) {
                g_node[n] = make_float4(1.0f / fmaxf(sqrtf(v0), 1e-6f), su0f,
                                        0.5f * __ldg(n_imp + n), 0.0f);
                if (two)
                    g_node[n1] = make_float4(1.0f / fmaxf(sqrtf(v1), 1e-6f), su1f,
                                             0.5f * __ldg(n_imp + n1), 0.0f);
            }
        }
    } else {
        // ---- edge scatter-add: 4 edges per thread ----
        int i = ((linear - nDotBlk - PREBLK) * (int)blockDim.x + (int)threadIdx.x) * 4;
        if (i + 3 < E) {
            int4 s = *(const int4*)(edge_src + i);
            int4 d = *(const int4*)(edge_dst + i);
            atomicAdd(&g_agg[d.x], g_sv[s.x]);
            atomicAdd(&g_agg[d.y], g_sv[s.y]);
            atomicAdd(&g_agg[d.z], g_sv[s.z]);
            atomicAdd(&g_agg[d.w], g_sv[s.w]);
        } else {
            for (int j = i; j < E; j++)
                atomicAdd(&g_agg[edge_dst[j]], g_sv[edge_src[j]]);
        }
    }
}

// K3: finalize — p_u from dot/agg/node tables + per-batch max (warp-merged).
__global__ void __launch_bounds__(256)
k_fin1(const int* __restrict__ u_ids,
       const int* __restrict__ batch_ptr, int M)
{
    int idx = blockIdx.x * blockDim.x + threadIdx.x;
    int m = idx * 4;
    bool full = (m + 3 < M);
    unsigned act = __ballot_sync(0xffffffffu, full);

    if (full) {
        int4   uu = *(const int4*)(u_ids + m);
        int4   bb = *(const int4*)(batch_ptr + m);
        float4 dt = *(const float4*)(g_dot + m);
        float4 ag = *(const float4*)(g_agg + m);

        float4 nd0 = __ldg((const float4*)g_node + uu.x);
        float4 nd1 = __ldg((const float4*)g_node + uu.y);
        float4 nd2 = __ldg((const float4*)g_node + uu.z);
        float4 nd3 = __ldg((const float4*)g_node + uu.w);
        float2 rs0 = __ldg(g_rootsc + bb.x);
        float2 rs1 = __ldg(g_rootsc + bb.y);
        float2 rs2 = __ldg(g_rootsc + bb.z);
        float2 rs3 = __ldg(g_rootsc + bb.w);

        float4 r;
        r.x = (dt.x * rs0.x * nd0.x + tanhf(ag.x + nd0.y)) * nd0.z * rs0.y;
        r.y = (dt.y * rs1.x * nd1.x + tanhf(ag.y + nd1.y)) * nd1.z * rs1.y;
        r.z = (dt.z * rs2.x * nd2.x + tanhf(ag.z + nd2.y)) * nd2.z * rs2.y;
        r.w = (dt.w * rs3.x * nd3.x + tanhf(ag.w + nd3.y)) * nd3.z * rs3.y;
        *(float4*)(g_pu + m) = r;

        unsigned kx = f2key(r.x), ky = f2key(r.y);
        unsigned kz = f2key(r.z), kw = f2key(r.w);
        bool uni4 = (bb.x == bb.w);
        unsigned kmax = kx > ky ? kx : ky;
        kmax = kmax > kz ? kmax : kz;
        kmax = kmax > kw ? kmax : kw;

        if (act == 0xffffffffu) {     // whole warp in this path: safe to shfl
            unsigned bFirst = __shfl_sync(0xffffffffu, (unsigned)bb.x, 0);
            bool warpUni = __all_sync(0xffffffffu,
                                      uni4 && (unsigned)bb.x == bFirst);
            if (warpUni) {
                #pragma unroll
                for (int o = 16; o; o >>= 1) {
                    unsigned t = __shfl_xor_sync(0xffffffffu, kmax, o);
                    kmax = kmax > t ? kmax : t;
                }
                if ((threadIdx.x & 31) == 0) atomicMax(&g_pnorm[bb.x], kmax);
                return;
            }
        }
        if (uni4) {
            atomicMax(&g_pnorm[bb.x], kmax);
        } else {
            atomicMax(&g_pnorm[bb.x], kx);
            atomicMax(&g_pnorm[bb.y], ky);
            atomicMax(&g_pnorm[bb.z], kz);
            atomicMax(&g_pnorm[bb.w], kw);
        }
    } else {
        for (int j = m; j < M; j++) {
            int u = __ldg(u_ids + j);
            int b = __ldg(batch_ptr + j);
            float4 nd = __ldg((const float4*)g_node + u);
            float2 rs = __ldg(g_rootsc + b);
            float p = (g_dot[j] * rs.x * nd.x + tanhf(g_agg[j] + nd.y))
                      * nd.z * rs.y;
            g_pu[j] = p;
            atomicMax(&g_pnorm[b], f2key(p));
        }
    }
}

// K5: normalize + nan/inf replace + clip (vectorized)
__global__ void k_final(const int* __restrict__ batch_ptr,
                        float* __restrict__ out, int M)
{
    int m = (blockIdx.x * blockDim.x + threadIdx.x) * 4;
    if (m + 3 < M) {
        int4   bp = *(const int4*)(batch_ptr + m);
        float4 pu = *(const float4*)(g_pu + m);
        float4 r;
        {
            float p = pu.x / key2f(g_pnorm[bp.x]) + 1.0f;
            if (isnan(p)) p = 0.0f; else if (isinf(p)) p = 1.0f;
            r.x = fminf(fmaxf(p, 1e-5f), 1.0f);
        }
        {
            float p = pu.y / key2f(g_pnorm[bp.y]) + 1.0f;
            if (isnan(p)) p = 0.0f; else if (isinf(p)) p = 1.0f;
            r.y = fminf(fmaxf(p, 1e-5f), 1.0f);
        }
        {
            float p = pu.z / key2f(g_pnorm[bp.z]) + 1.0f;
            if (isnan(p)) p = 0.0f; else if (isinf(p)) p = 1.0f;
            r.z = fminf(fmaxf(p, 1e-5f), 1.0f);
        }
        {
            float p = pu.w / key2f(g_pnorm[bp.w]) + 1.0f;
            if (isnan(p)) p = 0.0f; else if (isinf(p)) p = 1.0f;
            r.w = fminf(fmaxf(p, 1e-5f), 1.0f);
        }
        *(float4*)(out + m) = r;
    } else {
        for (int j = m; j < M; j++) {
            float p = g_pu[j] / key2f(g_pnorm[batch_ptr[j]]) + 1.0f;
            if (isnan(p)) p = 0.0f; else if (isinf(p)) p = 1.0f;
            out[j] = fminf(fmaxf(p, 1e-5f), 1.0f);
        }
    }
}

extern "C" void kernel_launch(void* const* d_in, const int* in_sizes, int n_in,
                              void* d_out, int out_size)
{
    const float* x           = (const float*)d_in[0];
    const float* w_ego_root  = (const float*)d_in[1];
    const float* w_ego_u     = (const float*)d_in[2];
    const float* w_layer_v   = (const float*)d_in[3];
    const float* w_layer_u   = (const float*)d_in[4];
    const float* n_imp       = (const float*)d_in[5];
    const float* budgets     = (const float*)d_in[6];
    const int*   batch_nodes = (const int*)d_in[7];
    const int*   u_ids       = (const int*)d_in[8];
    const int*   batch_ptr   = (const int*)d_in[9];
    const int*   edge_src    = (const int*)d_in[10];
    const int*   edge_dst    = (const int*)d_in[11];
    float* out = (float*)d_out;

    int B = in_sizes[7];
    int M = in_sizes[8];
    int E = in_sizes[10];
    int N = in_sizes[0] / FDIM;

    k_root<<<B, FDIM>>>(x, w_ego_root, w_ego_u, w_layer_v, budgets,
                        batch_nodes, B, M);

    int Mmain = M & ~3;
    int nDotWarps = (Mmain + CPW - 1) / CPW;
    int nDotBlk = (nDotWarps + 7) / 8;
    if (nDotBlk < 1) nDotBlk = 1;
    int edgeBlocks = (E / 4 + 255) / 256;
    int G = nDotBlk + PREBLK + edgeBlocks;
    int stripeSize = (G + 7) / 8;
    int gridBlocks = stripeSize * 8;     // <=7 idle pad blocks
    k_fused<<<gridBlocks, 256>>>(
        x, w_ego_u, w_layer_u, n_imp, edge_src, edge_dst,
        u_ids, batch_ptr, N, E, M, nDotBlk, G, stripeSize);

    k_fin1<<<(M / 4 + 255) / 256, 256>>>(u_ids, batch_ptr, M);

    k_final<<<(M / 4 + 255) / 256, 256>>>(batch_ptr, out, M);
}

// round 14
// speedup vs baseline: 1.0156x; 1.0156x over previous
#include <cuda_runtime.h>
#include <math.h>

#define FDIM 256
#define BMAX 1024
#define MMAX 500000
#define NMAX 200000
#define CPW  32      // candidates per dot-warp (8 iterations x 4)
#define PREBLK 1024  // blocks doing per-node precompute inside k_fused

// Scratch (allocation-free: __device__ globals)
__device__ float    g_groot[BMAX * FDIM];   // per-root x_r * w_ego_root * w_ego_u
__device__ float2   g_rootsc[BMAX];         // {1/max(nr,eps), budgets/200}
__device__ float    g_sv[BMAX];             // x_r . w_layer_v
__device__ unsigned g_pnorm[BMAX];          // encoded float max
__device__ float    g_agg[MMAX];            // segment_sum(sv[edge_src] -> edge_dst)
__device__ float    g_dot[MMAX];            // raw dot(x_u, g_b)
__device__ float    g_pu[MMAX];             // p_u before normalization
__device__ float4   g_node[NMAX];           // {1/max(nu,eps), su, 0.5*n_imp, 0}

__device__ __forceinline__ unsigned f2key(float f) {
    unsigned u = __float_as_uint(f);
    return (u & 0x80000000u) ? ~u : (u | 0x80000000u);
}
__device__ __forceinline__ float key2f(unsigned k) {
    unsigned u = (k & 0x80000000u) ? (k ^ 0x80000000u) : ~k;
    return __uint_as_float(u);
}
__device__ __forceinline__ float dot4(float4 a, float4 b) {
    return a.x * b.x + a.y * b.y + a.z * b.z + a.w * b.w;
}
__device__ __forceinline__ float sq4(float4 a, float4 w) {
    float t0 = a.x * w.x, t1 = a.y * w.y, t2 = a.z * w.z, t3 = a.w * w.w;
    return t0 * t0 + t1 * t1 + t2 * t2 + t3 * t3;
}

// K1: per-root precompute (one block per root) + zero g_agg (strided).
__global__ void k_root(const float* __restrict__ x,
                       const float* __restrict__ w_ego_root,
                       const float* __restrict__ w_ego_u,
                       const float* __restrict__ w_layer_v,
                       const float* __restrict__ budgets,
                       const int*   __restrict__ batch_nodes,
                       int B, int M)
{
    int b = blockIdx.x;
    int f = threadIdx.x;

    for (int j = b * FDIM + f; j < M; j += gridDim.x * FDIM) g_agg[j] = 0.0f;

    float xr = x[(size_t)batch_nodes[b] * FDIM + f];
    float h  = xr * w_ego_root[f];
    g_groot[b * FDIM + f] = h * w_ego_u[f];
    float s1 = h * h;
    float s2 = xr * w_layer_v[f];

    __shared__ float sh1[8], sh2[8];
    #pragma unroll
    for (int o = 16; o; o >>= 1) {
        s1 += __shfl_xor_sync(0xffffffffu, s1, o);
        s2 += __shfl_xor_sync(0xffffffffu, s2, o);
    }
    int w = f >> 5, l = f & 31;
    if (l == 0) { sh1[w] = s1; sh2[w] = s2; }
    __syncthreads();
    if (f == 0) {
        float t1 = 0.f, t2 = 0.f;
        #pragma unroll
        for (int i = 0; i < 8; i++) { t1 += sh1[i]; t2 += sh2[i]; }
        g_rootsc[b] = make_float2(1.0f / fmaxf(sqrtf(t1), 1e-6f),
                                  budgets[b] * (1.0f / 200.0f));
        g_sv[b] = t2;
        g_pnorm[b] = f2key(-INFINITY);
    }
}

// K2: one kernel, three independent block groups, launch-ordered
//   [0, nDotBlk)                    candidate dot gather (long pole, first)
//   [nDotBlk, nDotBlk+edgeBlk)      edge scatter-add (low-pollution, overlaps dot tail)
//   [nDotBlk+edgeBlk, ...)          per-node precompute (streaming, __ldcs, last)
__global__ void __launch_bounds__(256)
k_fused(const float* __restrict__ x,
        const float* __restrict__ w_ego_u,
        const float* __restrict__ w_layer_u,
        const float* __restrict__ n_imp,
        const int* __restrict__ edge_src,
        const int* __restrict__ edge_dst,
        const int* __restrict__ u_ids,
        const int* __restrict__ batch_ptr,
        int N, int E, int M, int nDotBlk, int edgeBlk)
{
    const float4* x4 = (const float4*)x;

    if (blockIdx.x < nDotBlk) {
        // ---- candidate dots: 8-lanes-per-candidate, 4 cands/warp-iter ----
        int lane  = threadIdx.x & 31;
        int gwarp = blockIdx.x * 8 + (threadIdx.x >> 5);
        int c = lane >> 3;          // candidate slot 0..3
        int s = lane & 7;           // sublane 0..7
        const float4* g4 = (const float4*)g_groot;

        int Mmain = M & ~3;

        // tail: grid-warp 0 handles [Mmain, M) with a 32-lane path
        if (gwarp == 0 && Mmain < M) {
            for (int m = Mmain; m < M; m++) {
                int u = __ldg(u_ids + m);
                int b = __ldg(batch_ptr + m);
                float4 xa = __ldg(x4 + (size_t)u * 64 + lane);
                float4 xb = __ldg(x4 + (size_t)u * 64 + lane + 32);
                float4 ta = __ldg(g4 + (size_t)b * 64 + lane);
                float4 tb = __ldg(g4 + (size_t)b * 64 + lane + 32);
                float d = dot4(xa, ta) + dot4(xb, tb);
                #pragma unroll
                for (int o = 16; o; o >>= 1)
                    d += __shfl_xor_sync(0xffffffffu, d, o);
                if (lane == 0) g_dot[m] = d;
            }
        }

        int base = gwarp * CPW;
        if (base >= Mmain) return;
        int lim = base + CPW; if (lim > Mmain) lim = Mmain;

        for (int m0 = base; m0 < lim; m0 += 4) {
            int4 uu = *(const int4*)(u_ids + m0);
            int4 bb = *(const int4*)(batch_ptr + m0);
            int u = (c == 0) ? uu.x : (c == 1) ? uu.y : (c == 2) ? uu.z : uu.w;
            int b = (c == 0) ? bb.x : (c == 1) ? bb.y : (c == 2) ? bb.z : bb.w;

            const float4* xr = x4 + (size_t)u * 64 + s;
            float4 xv0 = __ldg(xr);
            float4 xv1 = __ldg(xr + 8);
            float4 xv2 = __ldg(xr + 16);
            float4 xv3 = __ldg(xr + 24);
            float4 xv4 = __ldg(xr + 32);
            float4 xv5 = __ldg(xr + 40);
            float4 xv6 = __ldg(xr + 48);
            float4 xv7 = __ldg(xr + 56);

            const float4* gr = g4 + (size_t)b * 64 + s;
            float dot = dot4(xv0, __ldg(gr))
                      + dot4(xv1, __ldg(gr + 8))
                      + dot4(xv2, __ldg(gr + 16))
                      + dot4(xv3, __ldg(gr + 24))
                      + dot4(xv4, __ldg(gr + 32))
                      + dot4(xv5, __ldg(gr + 40))
                      + dot4(xv6, __ldg(gr + 48))
                      + dot4(xv7, __ldg(gr + 56));

            #pragma unroll
            for (int o = 4; o; o >>= 1)
                dot += __shfl_xor_sync(0xffffffffu, dot, o);

            if (s == 0) g_dot[m0 + c] = dot;   // 4 lanes, 16B coalesced
        }
    } else if (blockIdx.x < nDotBlk + edgeBlk) {
        // ---- edge scatter-add: 4 edges per thread ----
        int i = ((blockIdx.x - nDotBlk) * (int)blockDim.x + (int)threadIdx.x) * 4;
        if (i + 3 < E) {
            int4 s = *(const int4*)(edge_src + i);
            int4 d = *(const int4*)(edge_dst + i);
            atomicAdd(&g_agg[d.x], g_sv[s.x]);
            atomicAdd(&g_agg[d.y], g_sv[s.y]);
            atomicAdd(&g_agg[d.z], g_sv[s.z]);
            atomicAdd(&g_agg[d.w], g_sv[s.w]);
        } else {
            for (int j = i; j < E; j++)
                atomicAdd(&g_agg[edge_dst[j]], g_sv[edge_src[j]]);
        }
    } else {
        // ---- per-node precompute: {invnu, su, 0.5*n_imp}; streaming x ----
        int lane = threadIdx.x & 31;
        int gw = (blockIdx.x - nDotBlk - edgeBlk) * 8 + (threadIdx.x >> 5);
        int nw = PREBLK * 8;

        float4 wea = __ldg(((const float4*)w_ego_u)   + lane);
        float4 web = __ldg(((const float4*)w_ego_u)   + lane + 32);
        float4 wla = __ldg(((const float4*)w_layer_u) + lane);
        float4 wlb = __ldg(((const float4*)w_layer_u) + lane + 32);

        for (int n = gw * 2; n < N; n += nw * 2) {
            bool two = (n + 1 < N);
            float4 a0 = __ldcs(x4 + (size_t)n * 64 + lane);        // evict-first
            float4 b0 = __ldcs(x4 + (size_t)n * 64 + lane + 32);
            int n1 = two ? n + 1 : n;
            float4 a1 = __ldcs(x4 + (size_t)n1 * 64 + lane);
            float4 b1 = __ldcs(x4 + (size_t)n1 * 64 + lane + 32);

            float nu0 = sq4(a0, wea) + sq4(b0, web);
            float su0 = dot4(a0, wla) + dot4(b0, wlb);
            float nu1 = sq4(a1, wea) + sq4(b1, web);
            float su1 = dot4(a1, wla) + dot4(b1, wlb);

            nu0 += __shfl_xor_sync(0xffffffffu, nu0, 16);
            su0 += __shfl_xor_sync(0xffffffffu, su0, 16);
            nu1 += __shfl_xor_sync(0xffffffffu, nu1, 16);
            su1 += __shfl_xor_sync(0xffffffffu, su1, 16);
            bool hi16 = (lane & 16) != 0;
            float v0 = hi16 ? su0 : nu0;      // lanes<16: nu, >=16: su
            float v1 = hi16 ? su1 : nu1;
            #pragma unroll
            for (int o = 8; o; o >>= 1) {
                v0 += __shfl_xor_sync(0xffffffffu, v0, o);
                v1 += __shfl_xor_sync(0xffffffffu, v1, o);
            }
            float su0f = __shfl_sync(0xffffffffu, v0, 16);
            float su1f = __shfl_sync(0xffffffffu, v1, 16);
            if (lane == 0) {
                g_node[n] = make_float4(1.0f / fmaxf(sqrtf(v0), 1e-6f), su0f,
                                        0.5f * __ldg(n_imp + n), 0.0f);
                if (two)
                    g_node[n1] = make_float4(1.0f / fmaxf(sqrtf(v1), 1e-6f), su1f,
                                             0.5f * __ldg(n_imp + n1), 0.0f);
            }
        }
    }
}

// K3: finalize — p_u from dot/agg/node tables + per-batch max (warp-merged).
__global__ void __launch_bounds__(256)
k_fin1(const int* __restrict__ u_ids,
       const int* __restrict__ batch_ptr, int M)
{
    int idx = blockIdx.x * blockDim.x + threadIdx.x;
    int m = idx * 4;
    bool full = (m + 3 < M);
    unsigned act = __ballot_sync(0xffffffffu, full);

    if (full) {
        int4   uu = *(const int4*)(u_ids + m);
        int4   bb = *(const int4*)(batch_ptr + m);
        float4 dt = *(const float4*)(g_dot + m);
        float4 ag = *(const float4*)(g_agg + m);

        float4 nd0 = __ldg((const float4*)g_node + uu.x);
        float4 nd1 = __ldg((const float4*)g_node + uu.y);
        float4 nd2 = __ldg((const float4*)g_node + uu.z);
        float4 nd3 = __ldg((const float4*)g_node + uu.w);
        float2 rs0 = __ldg(g_rootsc + bb.x);
        float2 rs1 = __ldg(g_rootsc + bb.y);
        float2 rs2 = __ldg(g_rootsc + bb.z);
        float2 rs3 = __ldg(g_rootsc + bb.w);

        float4 r;
        r.x = (dt.x * rs0.x * nd0.x + tanhf(ag.x + nd0.y)) * nd0.z * rs0.y;
        r.y = (dt.y * rs1.x * nd1.x + tanhf(ag.y + nd1.y)) * nd1.z * rs1.y;
        r.z = (dt.z * rs2.x * nd2.x + tanhf(ag.z + nd2.y)) * nd2.z * rs2.y;
        r.w = (dt.w * rs3.x * nd3.x + tanhf(ag.w + nd3.y)) * nd3.z * rs3.y;
        *(float4*)(g_pu + m) = r;

        unsigned kx = f2key(r.x), ky = f2key(r.y);
        unsigned kz = f2key(r.z), kw = f2key(r.w);
        bool uni4 = (bb.x == bb.w);
        unsigned kmax = kx > ky ? kx : ky;
        kmax = kmax > kz ? kmax : kz;
        kmax = kmax > kw ? kmax : kw;

        if (act == 0xffffffffu) {     // whole warp in this path: safe to shfl
            unsigned bFirst = __shfl_sync(0xffffffffu, (unsigned)bb.x, 0);
            bool warpUni = __all_sync(0xffffffffu,
                                      uni4 && (unsigned)bb.x == bFirst);
            if (warpUni) {
                #pragma unroll
                for (int o = 16; o; o >>= 1) {
                    unsigned t = __shfl_xor_sync(0xffffffffu, kmax, o);
                    kmax = kmax > t ? kmax : t;
                }
                if ((threadIdx.x & 31) == 0) atomicMax(&g_pnorm[bb.x], kmax);
                return;
            }
        }
        if (uni4) {
            atomicMax(&g_pnorm[bb.x], kmax);
        } else {
            atomicMax(&g_pnorm[bb.x], kx);
            atomicMax(&g_pnorm[bb.y], ky);
            atomicMax(&g_pnorm[bb.z], kz);
            atomicMax(&g_pnorm[bb.w], kw);
        }
    } else {
        for (int j = m; j < M; j++) {
            int u = __ldg(u_ids + j);
            int b = __ldg(batch_ptr + j);
            float4 nd = __ldg((const float4*)g_node + u);
            float2 rs = __ldg(g_rootsc + b);
            float p = (g_dot[j] * rs.x * nd.x + tanhf(g_agg[j] + nd.y))
                      * nd.z * rs.y;
            g_pu[j] = p;
            atomicMax(&g_pnorm[b], f2key(p));
        }
    }
}

// K5: normalize + nan/inf replace + clip (vectorized)
__global__ void k_final(const int* __restrict__ batch_ptr,
                        float* __restrict__ out, int M)
{
    int m = (blockIdx.x * blockDim.x + threadIdx.x) * 4;
    if (m + 3 < M) {
        int4   bp = *(const int4*)(batch_ptr + m);
        float4 pu = *(const float4*)(g_pu + m);
        float4 r;
        {
            float p = pu.x / key2f(g_pnorm[bp.x]) + 1.0f;
            if (isnan(p)) p = 0.0f; else if (isinf(p)) p = 1.0f;
            r.x = fminf(fmaxf(p, 1e-5f), 1.0f);
        }
        {
            float p = pu.y / key2f(g_pnorm[bp.y]) + 1.0f;
            if (isnan(p)) p = 0.0f; else if (isinf(p)) p = 1.0f;
            r.y = fminf(fmaxf(p, 1e-5f), 1.0f);
        }
        {
            float p = pu.z / key2f(g_pnorm[bp.z]) + 1.0f;
            if (isnan(p)) p = 0.0f; else if (isinf(p)) p = 1.0f;
            r.z = fminf(fmaxf(p, 1e-5f), 1.0f);
        }
        {
            float p = pu.w / key2f(g_pnorm[bp.w]) + 1.0f;
            if (isnan(p)) p = 0.0f; else if (isinf(p)) p = 1.0f;
            r.w = fminf(fmaxf(p, 1e-5f), 1.0f);
        }
        *(float4*)(out + m) = r;
    } else {
        for (int j = m; j < M; j++) {
            float p = g_pu[j] / key2f(g_pnorm[batch_ptr[j]]) + 1.0f;
            if (isnan(p)) p = 0.0f; else if (isinf(p)) p = 1.0f;
            out[j] = fminf(fmaxf(p, 1e-5f), 1.0f);
        }
    }
}

extern "C" void kernel_launch(void* const* d_in, const int* in_sizes, int n_in,
                              void* d_out, int out_size)
{
    const float* x           = (const float*)d_in[0];
    const float* w_ego_root  = (const float*)d_in[1];
    const float* w_ego_u     = (const float*)d_in[2];
    const float* w_layer_v   = (const float*)d_in[3];
    const float* w_layer_u   = (const float*)d_in[4];
    const float* n_imp       = (const float*)d_in[5];
    const float* budgets     = (const float*)d_in[6];
    const int*   batch_nodes = (const int*)d_in[7];
    const int*   u_ids       = (const int*)d_in[8];
    const int*   batch_ptr   = (const int*)d_in[9];
    const int*   edge_src    = (const int*)d_in[10];
    const int*   edge_dst    = (const int*)d_in[11];
    float* out = (float*)d_out;

    int B = in_sizes[7];
    int M = in_sizes[8];
    int E = in_sizes[10];
    int N = in_sizes[0] / FDIM;

    k_root<<<B, FDIM>>>(x, w_ego_root, w_ego_u, w_layer_v, budgets,
                        batch_nodes, B, M);

    int Mmain = M & ~3;
    int nDotWarps = (Mmain + CPW - 1) / CPW;
    int nDotBlk = (nDotWarps + 7) / 8;
    if (nDotBlk < 1) nDotBlk = 1;
    int edgeBlocks = (E / 4 + 255) / 256;
    k_fused<<<nDotBlk + edgeBlocks + PREBLK, 256>>>(
        x, w_ego_u, w_layer_u, n_imp, edge_src, edge_dst,
        u_ids, batch_ptr, N, E, M, nDotBlk, edgeBlocks);

    k_fin1<<<(M / 4 + 255) / 256, 256>>>(u_ids, batch_ptr, M);

    k_final<<<(M / 4 + 255) / 256, 256>>>(batch_ptr, out, M);
}